// round 15
// baseline (speedup 1.0000x reference)
#include <cuda_runtime.h>
#include <cstdint>
#include <math.h>

#define Bv   32
#define Pv   196
#define ENCv 2048
#define DECv 512
#define EMBv 512
#define ATTv 512
#define Vv   32000
#define Lv   21
#define Tv   20
#define KS1v 4
#define KS2v 8

// ---------------- scratch ----------------
__device__ float g_att1 [(size_t)Bv * Pv * ATTv];    // 12.8 MB (sorted order)
__device__ float g_mean [Bv * ENCv];
__device__ float g_h    [Bv * DECv];
__device__ float g_c    [Bv * DECv];
__device__ float g_e    [Bv * Pv];
__device__ float g_x    [Bv * 2048];                 // gate*awe
__device__ float g_hall [(size_t)Tv * Bv * DECv];
__device__ float g_embA [(size_t)Tv * Bv * EMBv];    // gathered embeddings
__device__ float g_gemb [(size_t)Tv * Bv * 2048];    // emb @ W_ih[:, :512].T
__device__ float g_zero [2048];                      // stays zero (bias for Gemb)
__device__ float g_partA[(size_t)8 * Bv * 4608];     // GEMM1 / h0c0 partials
__device__ float g_partB[(size_t)KS2v * Bv * 2048];  // GEMM2 partials (Wih mid)
__device__ int   g_sort  [Bv];
__device__ int   g_declen[Bv];

__device__ __forceinline__ float sigmf(float x){ return 1.0f / (1.0f + expf(-x)); }

__device__ __forceinline__ uint32_t f2tf32(float x){
    uint32_t r; asm("cvt.rna.tf32.f32 %0, %1;" : "=r"(r) : "f"(x)); return r;
}

#define CP16(dst, src) asm volatile("cp.async.cg.shared.global [%0], [%1], 16;\n" :: "r"(dst), "l"(src))
#define CP_COMMIT()    asm volatile("cp.async.commit_group;\n")
#define CP_WAIT0()     asm volatile("cp.async.wait_group 0;\n")

// ---------------- setup kernels ----------------
__global__ void k_sort(const int* __restrict__ lens)
{
    __shared__ int s[Bv];
    int b = threadIdx.x;
    s[b] = lens[b];
    __syncthreads();
    int my = s[b], rank = 0;
    for (int j = 0; j < Bv; j++) {
        int lj = s[j];
        rank += (lj > my) || (lj == my && j < b);
    }
    g_sort[rank]   = b;
    g_declen[rank] = my - 1;
}

__global__ void k_mean(const float* __restrict__ enc)
{
    int b = blockIdx.x;
    int e = blockIdx.y * 256 + threadIdx.x;
    int src = g_sort[b];
    const float* in = enc + (size_t)src * Pv * ENCv + e;
    float s = 0.f;
    #pragma unroll 4
    for (int p = 0; p < Pv; p++) s += in[(size_t)p * ENCv];
    g_mean[b * ENCv + e] = s * (1.0f / (float)Pv);
}

__global__ void k_embg(const int* __restrict__ caps, const float* __restrict__ embW)
{
    int m = blockIdx.x;            // 0..639  (t*32+b)
    int t = m >> 5, b = m & 31;
    int cap = caps[g_sort[b] * Lv + t];
    const float4* src = (const float4*)(embW + (size_t)cap * EMBv);
    float4* dst = (float4*)(g_embA + (size_t)m * EMBv);
    dst[threadIdx.x] = src[threadIdx.x];   // 128 threads x float4 = 512
}

// ================= tf32 tensor-core GEMM, 128x128 tile =================
// C[m,n] = sum_k A[m,k]*W[n,k] + bias[n].  W row stride = wstride.
// mode 0: plain store (C row stride = N)
// mode 2: plain store, A rows indirected through g_sort (row = b*Pv+p)
#define TSTR 20

__global__ void __launch_bounds__(256) k_tgemm(
    const float* __restrict__ A, const float* __restrict__ W,
    const float* __restrict__ bias, float* __restrict__ C,
    int M, int N, int K, int wstride, int mode)
{
    __shared__ float As[2][128 * TSTR];
    __shared__ float Ws[2][128 * TSTR];

    const int tid  = threadIdx.x;
    const int lane = tid & 31;
    const int wid  = tid >> 5;
    const int wm   = wid >> 2;
    const int wn   = wid & 3;
    const int m0   = blockIdx.y * 128;
    const int n0   = blockIdx.x * 128;

    const int r0l = tid >> 2,          q0l = (tid & 3);
    const int r1l = (tid + 256) >> 2,  q1l = ((tid + 256) & 3);

    int r0g = m0 + r0l, r1g = m0 + r1l;
    if (mode == 2) {
        r0g = g_sort[r0g / Pv] * Pv + (r0g % Pv);
        r1g = g_sort[r1g / Pv] * Pv + (r1g % Pv);
    }
    const float* Ap0 = A + (size_t)r0g * K + q0l * 4;
    const float* Ap1 = A + (size_t)r1g * K + q1l * 4;
    const float* Wp0 = W + (size_t)(n0 + r0l) * wstride + q0l * 4;
    const float* Wp1 = W + (size_t)(n0 + r1l) * wstride + q1l * 4;

    uint32_t sA = (uint32_t)__cvta_generic_to_shared(&As[0][0]);
    uint32_t sW = (uint32_t)__cvta_generic_to_shared(&Ws[0][0]);
    const uint32_t bufSz = 128 * TSTR * 4;

    float acc[4][4][4];
    #pragma unroll
    for (int i = 0; i < 4; i++)
        #pragma unroll
        for (int j = 0; j < 4; j++)
            #pragma unroll
            for (int v = 0; v < 4; v++) acc[i][j][v] = 0.f;

    const int nk = K >> 4;

    CP16(sA + (uint32_t)((r0l * TSTR + q0l * 4) * 4), Ap0);
    CP16(sA + (uint32_t)((r1l * TSTR + q1l * 4) * 4), Ap1);
    CP16(sW + (uint32_t)((r0l * TSTR + q0l * 4) * 4), Wp0);
    CP16(sW + (uint32_t)((r1l * TSTR + q1l * 4) * 4), Wp1);
    CP_COMMIT();

    for (int kt = 0; kt < nk; kt++) {
        CP_WAIT0();
        __syncthreads();
        int buf = kt & 1;
        if (kt + 1 < nk) {
            uint32_t nb = (uint32_t)(buf ^ 1) * bufSz;
            int kn = (kt + 1) << 4;
            CP16(sA + nb + (uint32_t)((r0l * TSTR + q0l * 4) * 4), Ap0 + kn);
            CP16(sA + nb + (uint32_t)((r1l * TSTR + q1l * 4) * 4), Ap1 + kn);
            CP16(sW + nb + (uint32_t)((r0l * TSTR + q0l * 4) * 4), Wp0 + kn);
            CP16(sW + nb + (uint32_t)((r1l * TSTR + q1l * 4) * 4), Wp1 + kn);
            CP_COMMIT();
        }

        const float* a_s = As[buf];
        const float* w_s = Ws[buf];

        #pragma unroll
        for (int ks = 0; ks < 2; ks++) {
            int kk = ks * 8;
            uint32_t af[4][4], bf[4][2];
            #pragma unroll
            for (int mt = 0; mt < 4; mt++) {
                int r  = wm * 64 + mt * 16 + (lane >> 2);
                int cA = kk + (lane & 3);
                af[mt][0] = f2tf32(a_s[r * TSTR + cA]);
                af[mt][1] = f2tf32(a_s[(r + 8) * TSTR + cA]);
                af[mt][2] = f2tf32(a_s[r * TSTR + cA + 4]);
                af[mt][3] = f2tf32(a_s[(r + 8) * TSTR + cA + 4]);
            }
            #pragma unroll
            for (int nt = 0; nt < 4; nt++) {
                int n  = wn * 32 + nt * 8 + (lane >> 2);
                int kB = kk + (lane & 3);
                bf[nt][0] = f2tf32(w_s[n * TSTR + kB]);
                bf[nt][1] = f2tf32(w_s[n * TSTR + kB + 4]);
            }
            #pragma unroll
            for (int mt = 0; mt < 4; mt++)
                #pragma unroll
                for (int nt = 0; nt < 4; nt++) {
                    asm volatile(
                        "mma.sync.aligned.m16n8k8.row.col.f32.tf32.tf32.f32 "
                        "{%0,%1,%2,%3}, {%4,%5,%6,%7}, {%8,%9}, {%0,%1,%2,%3};\n"
                        : "+f"(acc[mt][nt][0]), "+f"(acc[mt][nt][1]),
                          "+f"(acc[mt][nt][2]), "+f"(acc[mt][nt][3])
                        : "r"(af[mt][0]), "r"(af[mt][1]), "r"(af[mt][2]), "r"(af[mt][3]),
                          "r"(bf[nt][0]), "r"(bf[nt][1]));
                }
        }
    }

    #pragma unroll
    for (int mt = 0; mt < 4; mt++) {
        int mA = m0 + wm * 64 + mt * 16 + (lane >> 2);
        #pragma unroll
        for (int nt = 0; nt < 4; nt++) {
            int n = n0 + wn * 32 + nt * 8 + (lane & 3) * 2;
            float bz0 = bias[n], bz1 = bias[n + 1];
            C[(size_t)mA * N + n]           = acc[mt][nt][0] + bz0;
            C[(size_t)mA * N + n + 1]       = acc[mt][nt][1] + bz1;
            C[(size_t)(mA + 8) * N + n]     = acc[mt][nt][2] + bz0;
            C[(size_t)(mA + 8) * N + n + 1] = acc[mt][nt][3] + bz1;
        }
    }
}

// ================= tf32 GEMM, M=32 (per-step preds, runs on stream s2) =================
// A: 32 x K.  Preds scatter for step t: out[b*T*V + t*V + n], 0 if t >= declen[b].
__global__ void __launch_bounds__(256) k_tgemm32(
    const float* __restrict__ A, const float* __restrict__ W,
    const float* __restrict__ bias, float* __restrict__ C,
    int K, int t)
{
    __shared__ float As[2][32 * TSTR];
    __shared__ float Ws[2][256 * TSTR];

    const int tid  = threadIdx.x;
    const int lane = tid & 31;
    const int wid  = tid >> 5;
    const int wm   = wid >> 2;          // 0..1
    const int wn   = wid & 3;           // 0..3
    const int n0   = blockIdx.x * 256;

    const int ra = tid >> 2, qa = (tid & 3);
    uint32_t sA = (uint32_t)__cvta_generic_to_shared(&As[0][0]);
    uint32_t sW = (uint32_t)__cvta_generic_to_shared(&Ws[0][0]);
    const uint32_t bufA = 32 * TSTR * 4, bufW = 256 * TSTR * 4;

    float acc[8][4];
    #pragma unroll
    for (int i = 0; i < 8; i++)
        #pragma unroll
        for (int v = 0; v < 4; v++) acc[i][v] = 0.f;

    const int nk = K >> 4;

    if (tid < 128) CP16(sA + (uint32_t)((ra * TSTR + qa * 4) * 4), A + (size_t)ra * K + qa * 4);
    #pragma unroll
    for (int i = 0; i < 4; i++) {
        int idx = tid + i * 256;
        int r = idx >> 2, q = idx & 3;
        CP16(sW + (uint32_t)((r * TSTR + q * 4) * 4), W + (size_t)(n0 + r) * K + q * 4);
    }
    CP_COMMIT();

    for (int kt = 0; kt < nk; kt++) {
        CP_WAIT0();
        __syncthreads();
        int buf = kt & 1;
        if (kt + 1 < nk) {
            uint32_t nbA = (uint32_t)(buf ^ 1) * bufA;
            uint32_t nbW = (uint32_t)(buf ^ 1) * bufW;
            int kn = (kt + 1) << 4;
            if (tid < 128) CP16(sA + nbA + (uint32_t)((ra * TSTR + qa * 4) * 4),
                                A + (size_t)ra * K + kn + qa * 4);
            #pragma unroll
            for (int i = 0; i < 4; i++) {
                int idx = tid + i * 256;
                int r = idx >> 2, q = idx & 3;
                CP16(sW + nbW + (uint32_t)((r * TSTR + q * 4) * 4),
                     W + (size_t)(n0 + r) * K + kn + q * 4);
            }
            CP_COMMIT();
        }

        const float* a_s = As[buf];
        const float* w_s = Ws[buf];

        #pragma unroll
        for (int ks = 0; ks < 2; ks++) {
            int kk = ks * 8;
            uint32_t af[4], bf[8][2];
            {
                int r  = wm * 16 + (lane >> 2);
                int cA = kk + (lane & 3);
                af[0] = f2tf32(a_s[r * TSTR + cA]);
                af[1] = f2tf32(a_s[(r + 8) * TSTR + cA]);
                af[2] = f2tf32(a_s[r * TSTR + cA + 4]);
                af[3] = f2tf32(a_s[(r + 8) * TSTR + cA + 4]);
            }
            #pragma unroll
            for (int nt = 0; nt < 8; nt++) {
                int n  = wn * 64 + nt * 8 + (lane >> 2);
                int kB = kk + (lane & 3);
                bf[nt][0] = f2tf32(w_s[n * TSTR + kB]);
                bf[nt][1] = f2tf32(w_s[n * TSTR + kB + 4]);
            }
            #pragma unroll
            for (int nt = 0; nt < 8; nt++) {
                asm volatile(
                    "mma.sync.aligned.m16n8k8.row.col.f32.tf32.tf32.f32 "
                    "{%0,%1,%2,%3}, {%4,%5,%6,%7}, {%8,%9}, {%0,%1,%2,%3};\n"
                    : "+f"(acc[nt][0]), "+f"(acc[nt][1]), "+f"(acc[nt][2]), "+f"(acc[nt][3])
                    : "r"(af[0]), "r"(af[1]), "r"(af[2]), "r"(af[3]),
                      "r"(bf[nt][0]), "r"(bf[nt][1]));
            }
        }
    }

    int r = wm * 16 + (lane >> 2);
    int b0 = r, b1 = r + 8;
    int ok0 = t < g_declen[b0];
    int ok1 = t < g_declen[b1];
    size_t base0 = (size_t)b0 * ((size_t)Tv * Vv) + (size_t)t * Vv;
    size_t base1 = (size_t)b1 * ((size_t)Tv * Vv) + (size_t)t * Vv;
    #pragma unroll
    for (int nt = 0; nt < 8; nt++) {
        int n = n0 + wn * 64 + nt * 8 + (lane & 3) * 2;
        float bz0 = bias[n], bz1 = bias[n + 1];
        C[base0 + n]     = ok0 ? (acc[nt][0] + bz0) : 0.f;
        C[base0 + n + 1] = ok0 ? (acc[nt][1] + bz1) : 0.f;
        C[base1 + n]     = ok1 ? (acc[nt][2] + bz0) : 0.f;
        C[base1 + n + 1] = ok1 ? (acc[nt][3] + bz1) : 0.f;
    }
}

// ---------------- weight source resolver (shared by small-M kernels) ----------------
__device__ __forceinline__ const float* w_src(int wmode,
    const float* W1, const float* W2, const float* W3, int n, int k, int K)
{
    if (wmode == 3) {
        if (n < 512)  return W1 + (size_t)n * 512 + k;
        if (n < 2560) return W2 + (size_t)(n - 512) * 512 + k;
        return W3 + (size_t)(n - 2560) * 512 + k;
    }
    if (wmode == 5) {
        return (n < 512) ? (W1 + (size_t)n * 2048 + k)
                         : (W2 + (size_t)(n - 512) * 2048 + k);
    }
    return W1 + (size_t)n * 2560 + 512 + k;   // wmode 4
}

// ============ small-M (M=32) split-K GEMM on tensor cores (3xTF32) ============
#define SBK 32
#define SSTR 36
#define NSTAGE 3
#define SM_A_FLOATS (32 * SSTR)
#define SM_W_FLOATS (128 * SSTR)
#define TS_SMEM ((NSTAGE * (SM_A_FLOATS + SM_W_FLOATS)) * 4)

__global__ void __launch_bounds__(256) k_tsgemm(
    const float* __restrict__ A, int K, int N, int wmode,
    const float* __restrict__ W1, const float* __restrict__ W2,
    const float* __restrict__ W3, float* __restrict__ part)
{
    extern __shared__ float sm[];
    float* sA = sm;
    float* sW = sm + NSTAGE * SM_A_FLOATS;

    const int tid  = threadIdx.x;
    const int lane = tid & 31;
    const int wid  = tid >> 5;
    const int wm   = wid >> 2;
    const int wn   = wid & 3;
    const int n0   = blockIdx.x * 128;
    const int Kc   = K / gridDim.y;
    const int kbase = blockIdx.y * Kc;
    const int nt   = Kc / SBK;

    uint32_t sAu = (uint32_t)__cvta_generic_to_shared(sA);
    uint32_t sWu = (uint32_t)__cvta_generic_to_shared(sW);

    const int ar = tid >> 3, aq = tid & 7;
    const uint32_t aOff = (uint32_t)((ar * SSTR + aq * 4) * 4);

    float acc[4][4];
    #pragma unroll
    for (int i = 0; i < 4; i++)
        #pragma unroll
        for (int v = 0; v < 4; v++) acc[i][v] = 0.f;

    #pragma unroll
    for (int s = 0; s < NSTAGE - 1; s++) {
        int kb = kbase + s * SBK;
        CP16(sAu + (uint32_t)(s * SM_A_FLOATS * 4) + aOff,
             A + (size_t)ar * K + kb + aq * 4);
        #pragma unroll
        for (int i = 0; i < 4; i++) {
            int idx = tid + i * 256;
            int r = idx >> 3, q = idx & 7;
            CP16(sWu + (uint32_t)((s * SM_W_FLOATS + r * SSTR + q * 4) * 4),
                 w_src(wmode, W1, W2, W3, n0 + r, kb + q * 4, K));
        }
        CP_COMMIT();
    }

    for (int it = 0; it < nt; it++) {
        asm volatile("cp.async.wait_group %0;\n" :: "n"(NSTAGE - 2));
        __syncthreads();

        if (it + NSTAGE - 1 < nt) {
            int s = (it + NSTAGE - 1) % NSTAGE;
            int kb = kbase + (it + NSTAGE - 1) * SBK;
            CP16(sAu + (uint32_t)(s * SM_A_FLOATS * 4) + aOff,
                 A + (size_t)ar * K + kb + aq * 4);
            #pragma unroll
            for (int i = 0; i < 4; i++) {
                int idx = tid + i * 256;
                int r = idx >> 3, q = idx & 7;
                CP16(sWu + (uint32_t)((s * SM_W_FLOATS + r * SSTR + q * 4) * 4),
                     w_src(wmode, W1, W2, W3, n0 + r, kb + q * 4, K));
            }
            CP_COMMIT();
        } else {
            CP_COMMIT();
        }

        const float* a_s = sA + (it % NSTAGE) * SM_A_FLOATS;
        const float* w_s = sW + (it % NSTAGE) * SM_W_FLOATS;

        #pragma unroll
        for (int kk = 0; kk < 4; kk++) {
            int c = kk * 8 + (lane & 3);
            int r = wm * 16 + (lane >> 2);
            float a0f = a_s[r * SSTR + c];
            float a1f = a_s[(r + 8) * SSTR + c];
            float a2f = a_s[r * SSTR + c + 4];
            float a3f = a_s[(r + 8) * SSTR + c + 4];
            uint32_t ab[4], arr[4];
            ab[0] = f2tf32(a0f); arr[0] = f2tf32(a0f - __uint_as_float(ab[0]));
            ab[1] = f2tf32(a1f); arr[1] = f2tf32(a1f - __uint_as_float(ab[1]));
            ab[2] = f2tf32(a2f); arr[2] = f2tf32(a2f - __uint_as_float(ab[2]));
            ab[3] = f2tf32(a3f); arr[3] = f2tf32(a3f - __uint_as_float(ab[3]));

            #pragma unroll
            for (int ntile = 0; ntile < 4; ntile++) {
                int n  = wn * 32 + ntile * 8 + (lane >> 2);
                int kB = kk * 8 + (lane & 3);
                float b0f = w_s[n * SSTR + kB];
                float b1f = w_s[n * SSTR + kB + 4];
                uint32_t bb[2], br[2];
                bb[0] = f2tf32(b0f); br[0] = f2tf32(b0f - __uint_as_float(bb[0]));
                bb[1] = f2tf32(b1f); br[1] = f2tf32(b1f - __uint_as_float(bb[1]));

                asm volatile(
                    "mma.sync.aligned.m16n8k8.row.col.f32.tf32.tf32.f32 "
                    "{%0,%1,%2,%3}, {%4,%5,%6,%7}, {%8,%9}, {%0,%1,%2,%3};\n"
                    : "+f"(acc[ntile][0]), "+f"(acc[ntile][1]),
                      "+f"(acc[ntile][2]), "+f"(acc[ntile][3])
                    : "r"(ab[0]), "r"(ab[1]), "r"(ab[2]), "r"(ab[3]),
                      "r"(bb[0]), "r"(bb[1]));
                asm volatile(
                    "mma.sync.aligned.m16n8k8.row.col.f32.tf32.tf32.f32 "
                    "{%0,%1,%2,%3}, {%4,%5,%6,%7}, {%8,%9}, {%0,%1,%2,%3};\n"
                    : "+f"(acc[ntile][0]), "+f"(acc[ntile][1]),
                      "+f"(acc[ntile][2]), "+f"(acc[ntile][3])
                    : "r"(arr[0]), "r"(arr[1]), "r"(arr[2]), "r"(arr[3]),
                      "r"(bb[0]), "r"(bb[1]));
                asm volatile(
                    "mma.sync.aligned.m16n8k8.row.col.f32.tf32.tf32.f32 "
                    "{%0,%1,%2,%3}, {%4,%5,%6,%7}, {%8,%9}, {%0,%1,%2,%3};\n"
                    : "+f"(acc[ntile][0]), "+f"(acc[ntile][1]),
                      "+f"(acc[ntile][2]), "+f"(acc[ntile][3])
                    : "r"(ab[0]), "r"(ab[1]), "r"(ab[2]), "r"(ab[3]),
                      "r"(br[0]), "r"(br[1]));
            }
        }
    }

    float* pp = part + (size_t)blockIdx.y * Bv * N;
    int r = wm * 16 + (lane >> 2);
    #pragma unroll
    for (int ntile = 0; ntile < 4; ntile++) {
        int n = n0 + wn * 32 + ntile * 8 + (lane & 3) * 2;
        pp[(size_t)r * N + n]           = acc[ntile][0];
        pp[(size_t)r * N + n + 1]       = acc[ntile][1];
        pp[(size_t)(r + 8) * N + n]     = acc[ntile][2];
        pp[(size_t)(r + 8) * N + n + 1] = acc[ntile][3];
    }
}

// fused h0/c0 split-K reduce (N=1024: h | c)
__global__ void k_red2(const float* __restrict__ bh, const float* __restrict__ bc)
{
    int idx = blockIdx.x * 256 + threadIdx.x;   // 32*1024
    int b = idx >> 10, n = idx & 1023;
    float s = 0.f;
    #pragma unroll
    for (int ks = 0; ks < 8; ks++) s += g_partA[((size_t)ks * Bv + b) * 1024 + n];
    if (n < 512) g_h[b * 512 + n]         = s + bh[n];
    else         g_c[b * 512 + (n - 512)] = s + bc[n - 512];
}

// e[b,p] = dot( relu(att1[b,p,:] + att2[b,:]), w_fa ); att2 reduced inline
__global__ void __launch_bounds__(256) k_e(const float* __restrict__ wfa,
                                           const float* __restrict__ b_da)
{
    __shared__ float s2[ATTv];
    __shared__ float sw[ATTv];
    int b = blockIdx.x, tid = threadIdx.x;
    for (int i = tid; i < ATTv; i += 256) {
        float a = b_da[i];
        #pragma unroll
        for (int ks = 0; ks < KS1v; ks++) a += g_partA[((size_t)(ks * Bv + b)) * 4608 + i];
        s2[i] = a;
        sw[i] = wfa[i];
    }
    __syncthreads();
    int w = tid >> 5, lane = tid & 31;
    #pragma unroll
    for (int i = 0; i < 2; i++) {
        int p = blockIdx.y * 16 + w * 2 + i;
        if (p < Pv) {
            const float* a1 = g_att1 + ((size_t)(b * Pv + p)) * ATTv;
            float s = 0.f;
            #pragma unroll
            for (int it = 0; it < 4; it++) {
                int k = it * 128 + lane * 4;
                float4 v  = *(const float4*)(a1 + k);
                float4 t2 = *(const float4*)(s2 + k);
                float4 wf = *(const float4*)(sw + k);
                s += fmaxf(v.x + t2.x, 0.f) * wf.x + fmaxf(v.y + t2.y, 0.f) * wf.y
                   + fmaxf(v.z + t2.z, 0.f) * wf.z + fmaxf(v.w + t2.w, 0.f) * wf.w;
            }
            #pragma unroll
            for (int off = 16; off; off >>= 1) s += __shfl_xor_sync(0xffffffffu, s, off);
            if (lane == 0) g_e[b * Pv + p] = s;
        }
    }
}

// fused: softmax(e) + awe chunk + gate reduce/sigmoid + x = gate*awe; q==0 writes alphas
__global__ void __launch_bounds__(256) k_aweS(
    const float* __restrict__ enc, const float* __restrict__ b_fb,
    float* __restrict__ out_alpha, int t)
{
    __shared__ float sal[Pv];
    __shared__ float red[256];
    int b = blockIdx.x, q = blockIdx.y, tid = threadIdx.x;
    float v = (tid < Pv) ? g_e[b * Pv + tid] : -3.4e38f;
    red[tid] = v; __syncthreads();
    for (int s = 128; s; s >>= 1) { if (tid < s) red[tid] = fmaxf(red[tid], red[tid + s]); __syncthreads(); }
    float mx = red[0]; __syncthreads();
    float ex = (tid < Pv) ? expf(v - mx) : 0.f;
    red[tid] = ex; __syncthreads();
    for (int s = 128; s; s >>= 1) { if (tid < s) red[tid] += red[tid + s]; __syncthreads(); }
    float inv = 1.0f / red[0];
    if (tid < Pv) {
        sal[tid] = ex * inv;
        if (q == 0)
            out_alpha[(size_t)b * Tv * Pv + (size_t)t * Pv + tid] =
                (t < g_declen[b]) ? ex * inv : 0.f;
    }
    __syncthreads();

    int e = q * 256 + tid;
    int srcb = g_sort[b];
    const float* ep = enc + (size_t)srcb * Pv * ENCv + e;
    float s = 0.f;
    #pragma unroll 4
    for (int p = 0; p < Pv; p++) s += sal[p] * ep[(size_t)p * ENCv];

    float gsum = b_fb[e];
    #pragma unroll
    for (int ks = 0; ks < KS1v; ks++) gsum += g_partA[((size_t)(ks * Bv + b)) * 4608 + 512 + e];
    g_x[b * 2048 + e] = sigmf(gsum) * s;
}

// reduce all gate partials + Gemb + biases -> LSTM pointwise + masked state update
__global__ void k_lstm(const float* __restrict__ b_ih, const float* __restrict__ b_hh, int t)
{
    int idx = blockIdx.x * 256 + threadIdx.x;   // 16384
    int b = idx >> 9, j = idx & 511;
    float g4[4];
    #pragma unroll
    for (int g = 0; g < 4; g++) {
        int n = g * 512 + j;
        float s = b_ih[n] + b_hh[n] + g_gemb[((size_t)t * Bv + b) * 2048 + n];
        #pragma unroll
        for (int ks = 0; ks < KS2v; ks++) s += g_partB[((size_t)(ks * Bv + b)) * 2048 + n];
        #pragma unroll
        for (int ks = 0; ks < KS1v; ks++) s += g_partA[((size_t)(ks * Bv + b)) * 4608 + 2560 + n];
        g4[g] = s;
    }
    float cn = sigmf(g4[1]) * g_c[idx] + sigmf(g4[0]) * tanhf(g4[2]);
    float hn = sigmf(g4[3]) * tanhf(cn);
    g_hall[((size_t)t * Bv + b) * DECv + j] = hn;
    if (t < g_declen[b]) { g_h[idx] = hn; g_c[idx] = cn; }
}

// ---------------- host launcher ----------------
extern "C" void kernel_launch(void* const* d_in, const int* in_sizes, int n_in,
                              void* d_out, int out_size)
{
    const float* enc  = (const float*)d_in[0];
    const int*   caps = (const int*)  d_in[1];
    const int*   lens = (const int*)  d_in[2];
    const float* embW = (const float*)d_in[3];
    const float* W_ea = (const float*)d_in[4];
    const float* b_ea = (const float*)d_in[5];
    const float* W_da = (const float*)d_in[6];
    const float* b_da = (const float*)d_in[7];
    const float* w_fa = (const float*)d_in[8];
    const float* W_ih = (const float*)d_in[10];
    const float* b_ih = (const float*)d_in[11];
    const float* W_hh = (const float*)d_in[12];
    const float* b_hh = (const float*)d_in[13];
    const float* W_h0 = (const float*)d_in[14];
    const float* b_h0 = (const float*)d_in[15];
    const float* W_c0 = (const float*)d_in[16];
    const float* b_c0 = (const float*)d_in[17];
    const float* W_fb = (const float*)d_in[18];
    const float* b_fb = (const float*)d_in[19];
    const float* W_fc = (const float*)d_in[20];
    const float* b_fc = (const float*)d_in[21];

    float* out       = (float*)d_out;
    float* out_alpha = out + (size_t)Bv * Tv * Vv;

    void* p;
    float *att1, *mean, *hall, *embA, *gemb, *zero, *partA, *partB, *x, *h;
    cudaGetSymbolAddress(&p, g_att1);  att1  = (float*)p;
    cudaGetSymbolAddress(&p, g_mean);  mean  = (float*)p;
    cudaGetSymbolAddress(&p, g_hall);  hall  = (float*)p;
    cudaGetSymbolAddress(&p, g_embA);  embA  = (float*)p;
    cudaGetSymbolAddress(&p, g_gemb);  gemb  = (float*)p;
    cudaGetSymbolAddress(&p, g_zero);  zero  = (float*)p;
    cudaGetSymbolAddress(&p, g_partA); partA = (float*)p;
    cudaGetSymbolAddress(&p, g_partB); partB = (float*)p;
    cudaGetSymbolAddress(&p, g_x);     x     = (float*)p;
    cudaGetSymbolAddress(&p, g_h);     h     = (float*)p;

    cudaFuncSetAttribute(k_tsgemm, cudaFuncAttributeMaxDynamicSharedMemorySize, TS_SMEM);

    static cudaStream_t s2;
    static cudaEvent_t evT[Tv], evDone;
    static bool inited = false;
    if (!inited) {
        cudaStreamCreateWithFlags(&s2, cudaStreamNonBlocking);
        for (int t = 0; t < Tv; t++) cudaEventCreateWithFlags(&evT[t], cudaEventDisableTiming);
        cudaEventCreateWithFlags(&evDone, cudaEventDisableTiming);
        inited = true;
    }

    // ---- setup (default stream) ----
    k_sort<<<1, Bv>>>(lens);
    k_mean<<<dim3(Bv, ENCv / 256), 256>>>(enc);
    k_tgemm<<<dim3(ATTv / 128, (Bv * Pv) / 128), 256>>>(enc, W_ea, b_ea, att1,
                                                        Bv * Pv, ATTv, ENCv, ENCv, 2);
    k_tsgemm<<<dim3(1024 / 128, 8), 256, TS_SMEM>>>(mean, ENCv, 1024, 5, W_h0, W_c0, nullptr, partA);
    k_red2<<<(Bv * 1024) / 256, 256>>>(b_h0, b_c0);
    k_embg<<<Tv * Bv, 128>>>(caps, embW);
    k_tgemm<<<dim3(2048 / 128, (Tv * Bv) / 128), 256>>>(embA, W_ih, zero, gemb,
                                                        Tv * Bv, 2048, EMBv, 2560, 0);

    // ---- recurrence; preds(t) forked onto s2 after k_lstm(t) ----
    for (int t = 0; t < Tv; t++) {
        k_tsgemm<<<dim3(4608 / 128, KS1v), 256, TS_SMEM>>>(h, DECv, 4608, 3, W_da, W_fb, W_hh, partA);
        k_e<<<dim3(Bv, 13), 256>>>(w_fa, b_da);
        k_aweS<<<dim3(Bv, 8), 256>>>(enc, b_fb, out_alpha, t);
        k_tsgemm<<<dim3(2048 / 128, KS2v), 256, TS_SMEM>>>(x, 2048, 2048, 4, W_ih, nullptr, nullptr, partB);
        k_lstm<<<(Bv * DECv) / 256, 256>>>(b_ih, b_hh, t);

        cudaEventRecord(evT[t], 0);
        cudaStreamWaitEvent(s2, evT[t], 0);
        k_tgemm32<<<Vv / 256, 256, 0, s2>>>(hall + (size_t)t * Bv * DECv, W_fc, b_fc,
                                            out, DECv, t);
    }

    // join s2 back into the default stream before capture ends
    cudaEventRecord(evDone, s2);
    cudaStreamWaitEvent(0, evDone, 0);
}

// round 16
// speedup vs baseline: 1.1941x; 1.1941x over previous
#include <cuda_runtime.h>
#include <cstdint>
#include <math.h>

#define Bv   32
#define Pv   196
#define ENCv 2048
#define DECv 512
#define EMBv 512
#define ATTv 512
#define Vv   32000
#define Lv   21
#define Tv   20
#define KS1v 4
#define KS2v 8

// ---------------- scratch ----------------
__device__ float g_att1 [(size_t)Bv * Pv * ATTv];    // 12.8 MB (sorted order)
__device__ float g_mean [Bv * ENCv];
__device__ float g_h    [Bv * DECv];
__device__ float g_c    [Bv * DECv];
__device__ float g_e    [Bv * Pv];
__device__ float g_x    [Bv * 2048];                 // gate*awe
__device__ float g_hall [(size_t)Tv * Bv * DECv];
__device__ float g_embA [(size_t)Tv * Bv * EMBv];    // gathered embeddings
__device__ float g_gemb [(size_t)Tv * Bv * 2048];    // emb @ W_ih[:, :512].T
__device__ float g_zero [2048];                      // stays zero (bias for Gemb)
__device__ float g_partA[(size_t)8 * Bv * 4608];     // GEMM1 / h0c0 partials
__device__ float g_partB[(size_t)KS2v * Bv * 2048];  // GEMM2 partials (Wih mid)
__device__ int   g_sort  [Bv];
__device__ int   g_declen[Bv];

__device__ __forceinline__ float sigmf(float x){ return 1.0f / (1.0f + expf(-x)); }

__device__ __forceinline__ uint32_t f2tf32(float x){
    uint32_t r; asm("cvt.rna.tf32.f32 %0, %1;" : "=r"(r) : "f"(x)); return r;
}

#define CP16(dst, src) asm volatile("cp.async.cg.shared.global [%0], [%1], 16;\n" :: "r"(dst), "l"(src))
#define CP_COMMIT()    asm volatile("cp.async.commit_group;\n")
#define CP_WAIT0()     asm volatile("cp.async.wait_group 0;\n")

// ---------------- setup kernels ----------------
__global__ void k_sort(const int* __restrict__ lens)
{
    __shared__ int s[Bv];
    int b = threadIdx.x;
    s[b] = lens[b];
    __syncthreads();
    int my = s[b], rank = 0;
    for (int j = 0; j < Bv; j++) {
        int lj = s[j];
        rank += (lj > my) || (lj == my && j < b);
    }
    g_sort[rank]   = b;
    g_declen[rank] = my - 1;
}

__global__ void k_mean(const float* __restrict__ enc)
{
    int b = blockIdx.x;
    int e = blockIdx.y * 256 + threadIdx.x;
    int src = g_sort[b];
    const float* in = enc + (size_t)src * Pv * ENCv + e;
    float s = 0.f;
    #pragma unroll 4
    for (int p = 0; p < Pv; p++) s += in[(size_t)p * ENCv];
    g_mean[b * ENCv + e] = s * (1.0f / (float)Pv);
}

__global__ void k_embg(const int* __restrict__ caps, const float* __restrict__ embW)
{
    int m = blockIdx.x;            // 0..639  (t*32+b)
    int t = m >> 5, b = m & 31;
    int cap = caps[g_sort[b] * Lv + t];
    const float4* src = (const float4*)(embW + (size_t)cap * EMBv);
    float4* dst = (float4*)(g_embA + (size_t)m * EMBv);
    dst[threadIdx.x] = src[threadIdx.x];   // 128 threads x float4 = 512
}

// ================= tf32 tensor-core GEMM, 128x256 tile, 64x64 warp tiles =================
// C[m,n] = sum_k A[m,k]*W[n,k] + bias[n].  W row stride = wstride.
// mode 0: plain store (C row stride = N)
// mode 1: preds scatter epilogue: m=(t*32+b) -> out[b*T*V + t*V + n], 0 if t>=declen[b]
// mode 2: plain store, A rows indirected through g_sort (row = b*Pv+p)
// Requires M%128==0, N%256==0, K%16==0.
#define TSTR 20
#define TG_A_FLOATS (128 * TSTR)
#define TG_W_FLOATS (256 * TSTR)
#define TG_SMEM ((2 * (TG_A_FLOATS + TG_W_FLOATS)) * 4)

__global__ void __launch_bounds__(256) k_tgemm(
    const float* __restrict__ A, const float* __restrict__ W,
    const float* __restrict__ bias, float* __restrict__ C,
    int M, int N, int K, int wstride, int mode)
{
    extern __shared__ float smg[];
    float* AsB = smg;                       // 2 x TG_A_FLOATS
    float* WsB = smg + 2 * TG_A_FLOATS;     // 2 x TG_W_FLOATS

    const int tid  = threadIdx.x;
    const int lane = tid & 31;
    const int wid  = tid >> 5;
    const int wm   = wid >> 2;              // 0..1  (64-row slab)
    const int wn   = wid & 3;               // 0..3  (64-col slab)
    const int m0   = blockIdx.y * 128;
    const int n0   = blockIdx.x * 256;

    // loader coords: A = 512 float4 (2/thread), W = 1024 float4 (4/thread)
    const int ra = tid >> 2, qa = tid & 3;  // ra 0..63, rows ra and ra+64 for A; ra+i*64 for W

    int r0g = m0 + ra, r1g = m0 + ra + 64;
    if (mode == 2) {
        r0g = g_sort[r0g / Pv] * Pv + (r0g % Pv);
        r1g = g_sort[r1g / Pv] * Pv + (r1g % Pv);
    }
    const float* Ap0 = A + (size_t)r0g * K + qa * 4;
    const float* Ap1 = A + (size_t)r1g * K + qa * 4;
    const float* Wp[4];
    #pragma unroll
    for (int i = 0; i < 4; i++)
        Wp[i] = W + (size_t)(n0 + ra + i * 64) * wstride + qa * 4;

    uint32_t sA = (uint32_t)__cvta_generic_to_shared(AsB);
    uint32_t sW = (uint32_t)__cvta_generic_to_shared(WsB);
    const uint32_t aRow0 = (uint32_t)((ra * TSTR + qa * 4) * 4);
    const uint32_t aRow1 = (uint32_t)(((ra + 64) * TSTR + qa * 4) * 4);

    float acc[4][8][4];
    #pragma unroll
    for (int i = 0; i < 4; i++)
        #pragma unroll
        for (int j = 0; j < 8; j++)
            #pragma unroll
            for (int v = 0; v < 4; v++) acc[i][j][v] = 0.f;

    const int nk = K >> 4;

    // prologue
    CP16(sA + aRow0, Ap0);
    CP16(sA + aRow1, Ap1);
    #pragma unroll
    for (int i = 0; i < 4; i++)
        CP16(sW + (uint32_t)(((ra + i * 64) * TSTR + qa * 4) * 4), Wp[i]);
    CP_COMMIT();

    for (int kt = 0; kt < nk; kt++) {
        CP_WAIT0();
        __syncthreads();
        int buf = kt & 1;
        if (kt + 1 < nk) {
            uint32_t nbA = (uint32_t)((buf ^ 1) * TG_A_FLOATS * 4);
            uint32_t nbW = (uint32_t)((buf ^ 1) * TG_W_FLOATS * 4);
            int kn = (kt + 1) << 4;
            CP16(sA + nbA + aRow0, Ap0 + kn);
            CP16(sA + nbA + aRow1, Ap1 + kn);
            #pragma unroll
            for (int i = 0; i < 4; i++)
                CP16(sW + nbW + (uint32_t)(((ra + i * 64) * TSTR + qa * 4) * 4), Wp[i] + kn);
            CP_COMMIT();
        }

        const float* a_s = AsB + buf * TG_A_FLOATS;
        const float* w_s = WsB + buf * TG_W_FLOATS;

        #pragma unroll
        for (int ks = 0; ks < 2; ks++) {
            int kk = ks * 8;
            uint32_t af[4][4], bf[8][2];
            #pragma unroll
            for (int mt = 0; mt < 4; mt++) {
                int r  = wm * 64 + mt * 16 + (lane >> 2);
                int cA = kk + (lane & 3);
                af[mt][0] = f2tf32(a_s[r * TSTR + cA]);
                af[mt][1] = f2tf32(a_s[(r + 8) * TSTR + cA]);
                af[mt][2] = f2tf32(a_s[r * TSTR + cA + 4]);
                af[mt][3] = f2tf32(a_s[(r + 8) * TSTR + cA + 4]);
            }
            #pragma unroll
            for (int nt = 0; nt < 8; nt++) {
                int n  = wn * 64 + nt * 8 + (lane >> 2);
                int kB = kk + (lane & 3);
                bf[nt][0] = f2tf32(w_s[n * TSTR + kB]);
                bf[nt][1] = f2tf32(w_s[n * TSTR + kB + 4]);
            }
            #pragma unroll
            for (int mt = 0; mt < 4; mt++)
                #pragma unroll
                for (int nt = 0; nt < 8; nt++) {
                    asm volatile(
                        "mma.sync.aligned.m16n8k8.row.col.f32.tf32.tf32.f32 "
                        "{%0,%1,%2,%3}, {%4,%5,%6,%7}, {%8,%9}, {%0,%1,%2,%3};\n"
                        : "+f"(acc[mt][nt][0]), "+f"(acc[mt][nt][1]),
                          "+f"(acc[mt][nt][2]), "+f"(acc[mt][nt][3])
                        : "r"(af[mt][0]), "r"(af[mt][1]), "r"(af[mt][2]), "r"(af[mt][3]),
                          "r"(bf[nt][0]), "r"(bf[nt][1]));
                }
        }
    }

    #pragma unroll
    for (int mt = 0; mt < 4; mt++) {
        int mA = m0 + wm * 64 + mt * 16 + (lane >> 2);
        #pragma unroll
        for (int nt = 0; nt < 8; nt++) {
            int n = n0 + wn * 64 + nt * 8 + (lane & 3) * 2;
            float bz0 = bias[n], bz1 = bias[n + 1];
            float v00 = acc[mt][nt][0] + bz0, v01 = acc[mt][nt][1] + bz1;
            float v10 = acc[mt][nt][2] + bz0, v11 = acc[mt][nt][3] + bz1;
            if (mode == 1) {
                int t0 = mA >> 5,       b0 = mA & 31;
                int t1 = (mA + 8) >> 5, b1 = (mA + 8) & 31;
                int ok0 = t0 < g_declen[b0];
                int ok1 = t1 < g_declen[b1];
                size_t o0 = (size_t)b0 * ((size_t)Tv * Vv) + (size_t)t0 * Vv + n;
                size_t o1 = (size_t)b1 * ((size_t)Tv * Vv) + (size_t)t1 * Vv + n;
                C[o0]     = ok0 ? v00 : 0.f;
                C[o0 + 1] = ok0 ? v01 : 0.f;
                C[o1]     = ok1 ? v10 : 0.f;
                C[o1 + 1] = ok1 ? v11 : 0.f;
            } else {
                C[(size_t)mA * N + n]           = v00;
                C[(size_t)mA * N + n + 1]       = v01;
                C[(size_t)(mA + 8) * N + n]     = v10;
                C[(size_t)(mA + 8) * N + n + 1] = v11;
            }
        }
    }
}

// ---------------- weight source resolver (shared by small-M kernels) ----------------
__device__ __forceinline__ const float* w_src(int wmode,
    const float* W1, const float* W2, const float* W3, int n, int k, int K)
{
    if (wmode == 3) {
        if (n < 512)  return W1 + (size_t)n * 512 + k;
        if (n < 2560) return W2 + (size_t)(n - 512) * 512 + k;
        return W3 + (size_t)(n - 2560) * 512 + k;
    }
    if (wmode == 5) {
        return (n < 512) ? (W1 + (size_t)n * 2048 + k)
                         : (W2 + (size_t)(n - 512) * 2048 + k);
    }
    return W1 + (size_t)n * 2560 + 512 + k;   // wmode 4
}

// ============ small-M (M=32) split-K GEMM on tensor cores (3xTF32) ============
#define SBK 32
#define SSTR 36
#define NSTAGE 3
#define SM_A_FLOATS (32 * SSTR)
#define SM_W_FLOATS (128 * SSTR)
#define TS_SMEM ((NSTAGE * (SM_A_FLOATS + SM_W_FLOATS)) * 4)

__global__ void __launch_bounds__(256) k_tsgemm(
    const float* __restrict__ A, int K, int N, int wmode,
    const float* __restrict__ W1, const float* __restrict__ W2,
    const float* __restrict__ W3, float* __restrict__ part)
{
    extern __shared__ float sm[];
    float* sA = sm;
    float* sW = sm + NSTAGE * SM_A_FLOATS;

    const int tid  = threadIdx.x;
    const int lane = tid & 31;
    const int wid  = tid >> 5;
    const int wm   = wid >> 2;
    const int wn   = wid & 3;
    const int n0   = blockIdx.x * 128;
    const int Kc   = K / gridDim.y;
    const int kbase = blockIdx.y * Kc;
    const int nt   = Kc / SBK;

    uint32_t sAu = (uint32_t)__cvta_generic_to_shared(sA);
    uint32_t sWu = (uint32_t)__cvta_generic_to_shared(sW);

    const int ar = tid >> 3, aq = tid & 7;
    const uint32_t aOff = (uint32_t)((ar * SSTR + aq * 4) * 4);

    float acc[4][4];
    #pragma unroll
    for (int i = 0; i < 4; i++)
        #pragma unroll
        for (int v = 0; v < 4; v++) acc[i][v] = 0.f;

    #pragma unroll
    for (int s = 0; s < NSTAGE - 1; s++) {
        int kb = kbase + s * SBK;
        CP16(sAu + (uint32_t)(s * SM_A_FLOATS * 4) + aOff,
             A + (size_t)ar * K + kb + aq * 4);
        #pragma unroll
        for (int i = 0; i < 4; i++) {
            int idx = tid + i * 256;
            int r = idx >> 3, q = idx & 7;
            CP16(sWu + (uint32_t)((s * SM_W_FLOATS + r * SSTR + q * 4) * 4),
                 w_src(wmode, W1, W2, W3, n0 + r, kb + q * 4, K));
        }
        CP_COMMIT();
    }

    for (int it = 0; it < nt; it++) {
        asm volatile("cp.async.wait_group %0;\n" :: "n"(NSTAGE - 2));
        __syncthreads();

        if (it + NSTAGE - 1 < nt) {
            int s = (it + NSTAGE - 1) % NSTAGE;
            int kb = kbase + (it + NSTAGE - 1) * SBK;
            CP16(sAu + (uint32_t)(s * SM_A_FLOATS * 4) + aOff,
                 A + (size_t)ar * K + kb + aq * 4);
            #pragma unroll
            for (int i = 0; i < 4; i++) {
                int idx = tid + i * 256;
                int r = idx >> 3, q = idx & 7;
                CP16(sWu + (uint32_t)((s * SM_W_FLOATS + r * SSTR + q * 4) * 4),
                     w_src(wmode, W1, W2, W3, n0 + r, kb + q * 4, K));
            }
            CP_COMMIT();
        } else {
            CP_COMMIT();
        }

        const float* a_s = sA + (it % NSTAGE) * SM_A_FLOATS;
        const float* w_s = sW + (it % NSTAGE) * SM_W_FLOATS;

        #pragma unroll
        for (int kk = 0; kk < 4; kk++) {
            int c = kk * 8 + (lane & 3);
            int r = wm * 16 + (lane >> 2);
            float a0f = a_s[r * SSTR + c];
            float a1f = a_s[(r + 8) * SSTR + c];
            float a2f = a_s[r * SSTR + c + 4];
            float a3f = a_s[(r + 8) * SSTR + c + 4];
            uint32_t ab[4], arr[4];
            ab[0] = f2tf32(a0f); arr[0] = f2tf32(a0f - __uint_as_float(ab[0]));
            ab[1] = f2tf32(a1f); arr[1] = f2tf32(a1f - __uint_as_float(ab[1]));
            ab[2] = f2tf32(a2f); arr[2] = f2tf32(a2f - __uint_as_float(ab[2]));
            ab[3] = f2tf32(a3f); arr[3] = f2tf32(a3f - __uint_as_float(ab[3]));

            #pragma unroll
            for (int ntile = 0; ntile < 4; ntile++) {
                int n  = wn * 32 + ntile * 8 + (lane >> 2);
                int kB = kk * 8 + (lane & 3);
                float b0f = w_s[n * SSTR + kB];
                float b1f = w_s[n * SSTR + kB + 4];
                uint32_t bb[2], br[2];
                bb[0] = f2tf32(b0f); br[0] = f2tf32(b0f - __uint_as_float(bb[0]));
                bb[1] = f2tf32(b1f); br[1] = f2tf32(b1f - __uint_as_float(bb[1]));

                asm volatile(
                    "mma.sync.aligned.m16n8k8.row.col.f32.tf32.tf32.f32 "
                    "{%0,%1,%2,%3}, {%4,%5,%6,%7}, {%8,%9}, {%0,%1,%2,%3};\n"
                    : "+f"(acc[ntile][0]), "+f"(acc[ntile][1]),
                      "+f"(acc[ntile][2]), "+f"(acc[ntile][3])
                    : "r"(ab[0]), "r"(ab[1]), "r"(ab[2]), "r"(ab[3]),
                      "r"(bb[0]), "r"(bb[1]));
                asm volatile(
                    "mma.sync.aligned.m16n8k8.row.col.f32.tf32.tf32.f32 "
                    "{%0,%1,%2,%3}, {%4,%5,%6,%7}, {%8,%9}, {%0,%1,%2,%3};\n"
                    : "+f"(acc[ntile][0]), "+f"(acc[ntile][1]),
                      "+f"(acc[ntile][2]), "+f"(acc[ntile][3])
                    : "r"(arr[0]), "r"(arr[1]), "r"(arr[2]), "r"(arr[3]),
                      "r"(bb[0]), "r"(bb[1]));
                asm volatile(
                    "mma.sync.aligned.m16n8k8.row.col.f32.tf32.tf32.f32 "
                    "{%0,%1,%2,%3}, {%4,%5,%6,%7}, {%8,%9}, {%0,%1,%2,%3};\n"
                    : "+f"(acc[ntile][0]), "+f"(acc[ntile][1]),
                      "+f"(acc[ntile][2]), "+f"(acc[ntile][3])
                    : "r"(ab[0]), "r"(ab[1]), "r"(ab[2]), "r"(ab[3]),
                      "r"(br[0]), "r"(br[1]));
            }
        }
    }

    float* pp = part + (size_t)blockIdx.y * Bv * N;
    int r = wm * 16 + (lane >> 2);
    #pragma unroll
    for (int ntile = 0; ntile < 4; ntile++) {
        int n = n0 + wn * 32 + ntile * 8 + (lane & 3) * 2;
        pp[(size_t)r * N + n]           = acc[ntile][0];
        pp[(size_t)r * N + n + 1]       = acc[ntile][1];
        pp[(size_t)(r + 8) * N + n]     = acc[ntile][2];
        pp[(size_t)(r + 8) * N + n + 1] = acc[ntile][3];
    }
}

// fused h0/c0 split-K reduce (N=1024: h | c)
__global__ void k_red2(const float* __restrict__ bh, const float* __restrict__ bc)
{
    int idx = blockIdx.x * 256 + threadIdx.x;   // 32*1024
    int b = idx >> 10, n = idx & 1023;
    float s = 0.f;
    #pragma unroll
    for (int ks = 0; ks < 8; ks++) s += g_partA[((size_t)ks * Bv + b) * 1024 + n];
    if (n < 512) g_h[b * 512 + n]         = s + bh[n];
    else         g_c[b * 512 + (n - 512)] = s + bc[n - 512];
}

// e[b,p] = dot( relu(att1[b,p,:] + att2[b,:]), w_fa ); att2 reduced inline
__global__ void __launch_bounds__(256) k_e(const float* __restrict__ wfa,
                                           const float* __restrict__ b_da)
{
    __shared__ float s2[ATTv];
    __shared__ float sw[ATTv];
    int b = blockIdx.x, tid = threadIdx.x;
    for (int i = tid; i < ATTv; i += 256) {
        float a = b_da[i];
        #pragma unroll
        for (int ks = 0; ks < KS1v; ks++) a += g_partA[((size_t)(ks * Bv + b)) * 4608 + i];
        s2[i] = a;
        sw[i] = wfa[i];
    }
    __syncthreads();
    int w = tid >> 5, lane = tid & 31;
    #pragma unroll
    for (int i = 0; i < 2; i++) {
        int p = blockIdx.y * 16 + w * 2 + i;
        if (p < Pv) {
            const float* a1 = g_att1 + ((size_t)(b * Pv + p)) * ATTv;
            float s = 0.f;
            #pragma unroll
            for (int it = 0; it < 4; it++) {
                int k = it * 128 + lane * 4;
                float4 v  = *(const float4*)(a1 + k);
                float4 t2 = *(const float4*)(s2 + k);
                float4 wf = *(const float4*)(sw + k);
                s += fmaxf(v.x + t2.x, 0.f) * wf.x + fmaxf(v.y + t2.y, 0.f) * wf.y
                   + fmaxf(v.z + t2.z, 0.f) * wf.z + fmaxf(v.w + t2.w, 0.f) * wf.w;
            }
            #pragma unroll
            for (int off = 16; off; off >>= 1) s += __shfl_xor_sync(0xffffffffu, s, off);
            if (lane == 0) g_e[b * Pv + p] = s;
        }
    }
}

// fused: softmax(e) + awe chunk + gate reduce/sigmoid + x = gate*awe; q==0 writes alphas
__global__ void __launch_bounds__(256) k_aweS(
    const float* __restrict__ enc, const float* __restrict__ b_fb,
    float* __restrict__ out_alpha, int t)
{
    __shared__ float sal[Pv];
    __shared__ float red[256];
    int b = blockIdx.x, q = blockIdx.y, tid = threadIdx.x;
    float v = (tid < Pv) ? g_e[b * Pv + tid] : -3.4e38f;
    red[tid] = v; __syncthreads();
    for (int s = 128; s; s >>= 1) { if (tid < s) red[tid] = fmaxf(red[tid], red[tid + s]); __syncthreads(); }
    float mx = red[0]; __syncthreads();
    float ex = (tid < Pv) ? expf(v - mx) : 0.f;
    red[tid] = ex; __syncthreads();
    for (int s = 128; s; s >>= 1) { if (tid < s) red[tid] += red[tid + s]; __syncthreads(); }
    float inv = 1.0f / red[0];
    if (tid < Pv) {
        sal[tid] = ex * inv;
        if (q == 0)
            out_alpha[(size_t)b * Tv * Pv + (size_t)t * Pv + tid] =
                (t < g_declen[b]) ? ex * inv : 0.f;
    }
    __syncthreads();

    int e = q * 256 + tid;
    int srcb = g_sort[b];
    const float* ep = enc + (size_t)srcb * Pv * ENCv + e;
    float s = 0.f;
    #pragma unroll 4
    for (int p = 0; p < Pv; p++) s += sal[p] * ep[(size_t)p * ENCv];

    float gsum = b_fb[e];
    #pragma unroll
    for (int ks = 0; ks < KS1v; ks++) gsum += g_partA[((size_t)(ks * Bv + b)) * 4608 + 512 + e];
    g_x[b * 2048 + e] = sigmf(gsum) * s;
}

// reduce all gate partials + Gemb + biases -> LSTM pointwise + masked state update
__global__ void k_lstm(const float* __restrict__ b_ih, const float* __restrict__ b_hh, int t)
{
    int idx = blockIdx.x * 256 + threadIdx.x;   // 16384
    int b = idx >> 9, j = idx & 511;
    float g4[4];
    #pragma unroll
    for (int g = 0; g < 4; g++) {
        int n = g * 512 + j;
        float s = b_ih[n] + b_hh[n] + g_gemb[((size_t)t * Bv + b) * 2048 + n];
        #pragma unroll
        for (int ks = 0; ks < KS2v; ks++) s += g_partB[((size_t)(ks * Bv + b)) * 2048 + n];
        #pragma unroll
        for (int ks = 0; ks < KS1v; ks++) s += g_partA[((size_t)(ks * Bv + b)) * 4608 + 2560 + n];
        g4[g] = s;
    }
    float cn = sigmf(g4[1]) * g_c[idx] + sigmf(g4[0]) * tanhf(g4[2]);
    float hn = sigmf(g4[3]) * tanhf(cn);
    g_hall[((size_t)t * Bv + b) * DECv + j] = hn;
    if (t < g_declen[b]) { g_h[idx] = hn; g_c[idx] = cn; }
}

// ---------------- host launcher (default stream only) ----------------
extern "C" void kernel_launch(void* const* d_in, const int* in_sizes, int n_in,
                              void* d_out, int out_size)
{
    const float* enc  = (const float*)d_in[0];
    const int*   caps = (const int*)  d_in[1];
    const int*   lens = (const int*)  d_in[2];
    const float* embW = (const float*)d_in[3];
    const float* W_ea = (const float*)d_in[4];
    const float* b_ea = (const float*)d_in[5];
    const float* W_da = (const float*)d_in[6];
    const float* b_da = (const float*)d_in[7];
    const float* w_fa = (const float*)d_in[8];
    const float* W_ih = (const float*)d_in[10];
    const float* b_ih = (const float*)d_in[11];
    const float* W_hh = (const float*)d_in[12];
    const float* b_hh = (const float*)d_in[13];
    const float* W_h0 = (const float*)d_in[14];
    const float* b_h0 = (const float*)d_in[15];
    const float* W_c0 = (const float*)d_in[16];
    const float* b_c0 = (const float*)d_in[17];
    const float* W_fb = (const float*)d_in[18];
    const float* b_fb = (const float*)d_in[19];
    const float* W_fc = (const float*)d_in[20];
    const float* b_fc = (const float*)d_in[21];

    float* out       = (float*)d_out;
    float* out_alpha = out + (size_t)Bv * Tv * Vv;

    void* p;
    float *att1, *mean, *hall, *embA, *gemb, *zero, *partA, *partB, *x, *h;
    cudaGetSymbolAddress(&p, g_att1);  att1  = (float*)p;
    cudaGetSymbolAddress(&p, g_mean);  mean  = (float*)p;
    cudaGetSymbolAddress(&p, g_hall);  hall  = (float*)p;
    cudaGetSymbolAddress(&p, g_embA);  embA  = (float*)p;
    cudaGetSymbolAddress(&p, g_gemb);  gemb  = (float*)p;
    cudaGetSymbolAddress(&p, g_zero);  zero  = (float*)p;
    cudaGetSymbolAddress(&p, g_partA); partA = (float*)p;
    cudaGetSymbolAddress(&p, g_partB); partB = (float*)p;
    cudaGetSymbolAddress(&p, g_x);     x     = (float*)p;
    cudaGetSymbolAddress(&p, g_h);     h     = (float*)p;

    cudaFuncSetAttribute(k_tsgemm, cudaFuncAttributeMaxDynamicSharedMemorySize, TS_SMEM);
    cudaFuncSetAttribute(k_tgemm,  cudaFuncAttributeMaxDynamicSharedMemorySize, TG_SMEM);

    // ---- setup ----
    k_sort<<<1, Bv>>>(lens);
    k_mean<<<dim3(Bv, ENCv / 256), 256>>>(enc);
    // att1 = enc[sort] @ W_ea.T + b_ea  (tf32, indirect A rows)
    k_tgemm<<<dim3(ATTv / 256, (Bv * Pv) / 128), 256, TG_SMEM>>>(enc, W_ea, b_ea, att1,
                                                                 Bv * Pv, ATTv, ENCv, ENCv, 2);
    // h0 & c0 fused: N=1024, K=2048, ksplit 8 (tensor cores, 3xTF32)
    k_tsgemm<<<dim3(1024 / 128, 8), 256, TS_SMEM>>>(mean, ENCv, 1024, 5, W_h0, W_c0, nullptr, partA);
    k_red2<<<(Bv * 1024) / 256, 256>>>(b_h0, b_c0);
    // Gemb = emb(caps) @ W_ih[:, :512].T   (tf32, all timesteps at once)
    k_embg<<<Tv * Bv, 128>>>(caps, embW);
    k_tgemm<<<dim3(2048 / 256, (Tv * Bv) / 128), 256, TG_SMEM>>>(embA, W_ih, zero, gemb,
                                                                 Tv * Bv, 2048, EMBv, 2560, 0);

    // ---- recurrence: 5 kernels per step ----
    for (int t = 0; t < Tv; t++) {
        // GEMM1: h -> [att2 | gate | W_hh h], N=4608, K=512, ksplit 4 (tensor cores)
        k_tsgemm<<<dim3(4608 / 128, KS1v), 256, TS_SMEM>>>(h, DECv, 4608, 3, W_da, W_fb, W_hh, partA);
        k_e<<<dim3(Bv, 13), 256>>>(w_fa, b_da);
        k_aweS<<<dim3(Bv, 8), 256>>>(enc, b_fb, out_alpha, t);
        // GEMM2: (gate*awe) @ W_ih[:, 512:2560].T, N=2048, K=2048, ksplit 8 (tensor cores)
        k_tsgemm<<<dim3(2048 / 128, KS2v), 256, TS_SMEM>>>(x, 2048, 2048, 4, W_ih, nullptr, nullptr, partB);
        k_lstm<<<(Bv * DECv) / 256, 256>>>(b_ih, b_hh, t);
    }

    // predictions: (T*B) x V tf32 GEMM with mask+scatter epilogue
    k_tgemm<<<dim3(Vv / 256, (Tv * Bv) / 128), 256, TG_SMEM>>>(hall, W_fc, b_fc, out,
                                                               Tv * Bv, Vv, DECv, DECv, 1);
}